// round 5
// baseline (speedup 1.0000x reference)
#include <cuda_runtime.h>

#define BATCH 512
#define DDIM  64
#define TLEN  256
#define HID   100
#define G3    300
#define NBLK  128
#define RPB   4
#define NT    320
#define STC   65            // D+1 state channels
#define SROW  (STC*RPB)     // 260
#define HROW  (HID*RPB)     // 400

__device__ float g_states[NBLK * TLEN * SROW];
__device__ float g_hback [NBLK * (TLEN + 1) * HROW];

struct __align__(16) Smem {
    float sU [HID * G3];       // bgru_U  (120000 B)
    float sWb[STC * G3];       // bgru_W  ( 78000 B)
    float stage[2 * G3 * RPB]; // 9600 B
    float xs [SROW];
    float hsF[HROW];
    float hsB[HROW];
    float hb4[HROW];
    float dec4[50 * RPB];
    float bF[2 * G3];
    float bB[2 * G3];
    int   obs[TLEN];
};

__device__ __forceinline__ float sigf(float x) { return 1.0f / (1.0f + __expf(-x)); }

// gate nonlinearity phase; stage = gi[300][4] then gh[300][4]
__device__ __forceinline__ void gru_gates(float* stage, float* hs, float* gdict, int tid)
{
    __syncthreads();
    for (int idx = tid; idx < RPB * HID; idx += NT) {
        int i = idx >> 2, r = idx & 3;
        float giz = stage[i * RPB + r];
        float gir = stage[(HID + i) * RPB + r];
        float gin = stage[(2 * HID + i) * RPB + r];
        const float* sg = stage + G3 * RPB;
        float ghz = sg[i * RPB + r];
        float ghr = sg[(HID + i) * RPB + r];
        float ghn = sg[(2 * HID + i) * RPB + r];
        float z  = sigf(giz + ghz);
        float rr = sigf(gir + ghr);
        float n  = tanhf(fmaf(rr, ghn, gin));
        float hnew = z * hs[idx] + (1.0f - z) * n;
        hs[idx] = hnew;
        if (gdict) gdict[idx] = hnew;
    }
    __syncthreads();
}

// backward GRU step: x from smem (65ch) or zero-input; W & U in shared
template<bool HASX>
__device__ __forceinline__ void gru_step_back(const float* __restrict__ Ws,
                                              const float* __restrict__ Us,
                                              const float* __restrict__ bias,
                                              const float* __restrict__ xs,
                                              float* hs, float* stage, float* gdict, int tid)
{
    if (tid < G3) {
        int j = tid;
        float b0 = bias[j], b1 = bias[G3 + j];
        float gi0 = b0, gi1 = b0, gi2 = b0, gi3 = b0;
        float gh0 = b1, gh1 = b1, gh2 = b1, gh3 = b1;
        if (HASX) {
#pragma unroll 5
            for (int k = 0; k < STC; k++) {
                float4 xv = reinterpret_cast<const float4*>(xs)[k];
                float  w  = Ws[k * G3 + j];
                gi0 = fmaf(xv.x, w, gi0); gi1 = fmaf(xv.y, w, gi1);
                gi2 = fmaf(xv.z, w, gi2); gi3 = fmaf(xv.w, w, gi3);
            }
        }
#pragma unroll 5
        for (int k = 0; k < HID; k++) {
            float4 hv = reinterpret_cast<const float4*>(hs)[k];
            float  u  = Us[k * G3 + j];
            gh0 = fmaf(hv.x, u, gh0); gh1 = fmaf(hv.y, u, gh1);
            gh2 = fmaf(hv.z, u, gh2); gh3 = fmaf(hv.w, u, gh3);
        }
        stage[j * RPB + 0] = gi0; stage[j * RPB + 1] = gi1;
        stage[j * RPB + 2] = gi2; stage[j * RPB + 3] = gi3;
        float* sg = stage + G3 * RPB;
        sg[j * RPB + 0] = gh0; sg[j * RPB + 1] = gh1;
        sg[j * RPB + 2] = gh2; sg[j * RPB + 3] = gh3;
    }
    gru_gates(stage, hs, gdict, tid);
}

// forward GRU: input = state channels 1..64; W streamed (L2), U column in regs
__device__ __forceinline__ void gru_step_fwd(const float ureg[HID],
                                             const float* __restrict__ Wg,
                                             const float* __restrict__ bias,
                                             const float* __restrict__ xs,
                                             float* hs, float* stage, int tid)
{
    if (tid < G3) {
        int j = tid;
        float b0 = bias[j], b1 = bias[G3 + j];
        float gi0 = b0, gi1 = b0, gi2 = b0, gi3 = b0;
        float gh0 = b1, gh1 = b1, gh2 = b1, gh3 = b1;
#pragma unroll 4
        for (int k = 0; k < DDIM; k++) {
            float4 xv = reinterpret_cast<const float4*>(xs)[k + 1];
            float  w  = __ldg(&Wg[k * G3 + j]);
            gi0 = fmaf(xv.x, w, gi0); gi1 = fmaf(xv.y, w, gi1);
            gi2 = fmaf(xv.z, w, gi2); gi3 = fmaf(xv.w, w, gi3);
        }
#pragma unroll
        for (int k = 0; k < HID; k++) {
            float4 hv = reinterpret_cast<const float4*>(hs)[k];
            float  u  = ureg[k];
            gh0 = fmaf(hv.x, u, gh0); gh1 = fmaf(hv.y, u, gh1);
            gh2 = fmaf(hv.z, u, gh2); gh3 = fmaf(hv.w, u, gh3);
        }
        stage[j * RPB + 0] = gi0; stage[j * RPB + 1] = gi1;
        stage[j * RPB + 2] = gi2; stage[j * RPB + 3] = gi3;
        float* sg = stage + G3 * RPB;
        sg[j * RPB + 0] = gh0; sg[j * RPB + 1] = gh1;
        sg[j * RPB + 2] = gh2; sg[j * RPB + 3] = gh3;
    }
    gru_gates(stage, hs, nullptr, tid);
}

// dec = relu([h;hb] @ dec_W[lvl] + b); mean = dec @ mean_W[lvl] + b; write (mean,1)
__device__ __forceinline__ void decoder_event(int lvl,
                                              const float* __restrict__ decW,
                                              const float* __restrict__ decB,
                                              const float* __restrict__ meanW,
                                              const float* __restrict__ meanB,
                                              const float* hsF, const float* hb4,
                                              float* dec4, float* stage,
                                              float* gout, int tid)
{
    if (tid < 250) {                         // [4,200]@[200,50], k in 5 groups of 40
        int j = tid % 50, kg = tid / 50;
        float a0 = 0.f, a1 = 0.f, a2 = 0.f, a3 = 0.f;
        const float* Wl = decW + lvl * 200 * 50;
        int kbeg = kg * 40;
#pragma unroll 8
        for (int kk = 0; kk < 40; kk++) {
            int k = kbeg + kk;
            const float* src = (k < HID) ? (hsF + k * RPB) : (hb4 + (k - HID) * RPB);
            float4 hv = *reinterpret_cast<const float4*>(src);
            float  w  = __ldg(&Wl[k * 50 + j]);
            a0 = fmaf(hv.x, w, a0); a1 = fmaf(hv.y, w, a1);
            a2 = fmaf(hv.z, w, a2); a3 = fmaf(hv.w, w, a3);
        }
        stage[tid * 4 + 0] = a0; stage[tid * 4 + 1] = a1;
        stage[tid * 4 + 2] = a2; stage[tid * 4 + 3] = a3;
    }
    __syncthreads();
    if (tid < 50) {
        float b = __ldg(&decB[lvl * 50 + tid]);
        float s0 = b, s1 = b, s2 = b, s3 = b;
#pragma unroll
        for (int g = 0; g < 5; g++) {
            int base = (g * 50 + tid) * 4;
            s0 += stage[base + 0]; s1 += stage[base + 1];
            s2 += stage[base + 2]; s3 += stage[base + 3];
        }
        dec4[tid * 4 + 0] = fmaxf(s0, 0.f); dec4[tid * 4 + 1] = fmaxf(s1, 0.f);
        dec4[tid * 4 + 2] = fmaxf(s2, 0.f); dec4[tid * 4 + 3] = fmaxf(s3, 0.f);
    }
    __syncthreads();
    {                                        // [4,50]@[50,64], k in 5 groups of 10
        int j = tid % DDIM, kg = tid / DDIM;
        float m0 = 0.f, m1 = 0.f, m2 = 0.f, m3 = 0.f;
        const float* Ml = meanW + lvl * 50 * DDIM;
        int kbeg = kg * 10;
#pragma unroll
        for (int kk = 0; kk < 10; kk++) {
            int k = kbeg + kk;
            float4 dv = *reinterpret_cast<const float4*>(dec4 + k * RPB);
            float  w  = __ldg(&Ml[k * DDIM + j]);
            m0 = fmaf(dv.x, w, m0); m1 = fmaf(dv.y, w, m1);
            m2 = fmaf(dv.z, w, m2); m3 = fmaf(dv.w, w, m3);
        }
        stage[tid * 4 + 0] = m0; stage[tid * 4 + 1] = m1;
        stage[tid * 4 + 2] = m2; stage[tid * 4 + 3] = m3;
    }
    __syncthreads();
    if (tid < DDIM) {
        float b = __ldg(&meanB[lvl * DDIM + tid]);
        float s0 = b, s1 = b, s2 = b, s3 = b;
#pragma unroll
        for (int g = 0; g < 5; g++) {
            int base = (g * DDIM + tid) * 4;
            s0 += stage[base + 0]; s1 += stage[base + 1];
            s2 += stage[base + 2]; s3 += stage[base + 3];
        }
        gout[tid * RPB + 0] = s0; gout[tid * RPB + 1] = s1;
        gout[tid * RPB + 2] = s2; gout[tid * RPB + 3] = s3;
    }
    if (tid >= DDIM && tid < DDIM + RPB) gout[DDIM * RPB + (tid - DDIM)] = 1.0f;
    __syncthreads();
}

__global__ void __launch_bounds__(NT, 1)
naomi_kernel(const float* __restrict__ a,
             const float* __restrict__ gruW,  const float* __restrict__ gruU,
             const float* __restrict__ gruB,
             const float* __restrict__ bgruW, const float* __restrict__ bgruU,
             const float* __restrict__ bgruB,
             const float* __restrict__ decW,  const float* __restrict__ decB,
             const float* __restrict__ meanW, const float* __restrict__ meanB,
             float* __restrict__ out)
{
    extern __shared__ __align__(16) char smraw[];
    Smem* sm = reinterpret_cast<Smem*>(smraw);
    const int tid = threadIdx.x;
    const int bid = blockIdx.x;

    for (int i = tid; i < HID * G3; i += NT) sm->sU[i]  = bgruU[i];
    for (int i = tid; i < STC * G3; i += NT) sm->sWb[i] = bgruW[i];
    for (int i = tid; i < 2 * G3;   i += NT) { sm->bF[i] = gruB[i]; sm->bB[i] = bgruB[i]; }

    float ureg[HID];
#pragma unroll
    for (int k = 0; k < HID; k++) ureg[k] = (tid < G3) ? gruU[k * G3 + tid] : 0.0f;

    for (int t = tid; t < TLEN; t += NT) sm->obs[t] = (a[t * 3 + 2] > 0.5f) ? 1 : 0;

    float* gst = g_states + bid * TLEN * SROW;
    float* ghb = g_hback  + bid * (TLEN + 1) * HROW;
    const int b0row = bid * RPB;
    for (int idx = tid; idx < RPB * STC * TLEN; idx += NT) {
        int t = idx & (TLEN - 1);
        int tmp = idx >> 8;
        int k = tmp % STC, r = tmp / STC;
        int b = b0row + r;
        float v = (k < DDIM) ? a[((b * DDIM + k) * TLEN + t) * 3]
                             : a[((b * DDIM) * TLEN + t) * 3 + 2];
        gst[t * SROW + k * RPB + r] = v;
    }
    for (int i = tid; i < HROW; i += NT) { sm->hsB[i] = 0.f; ghb[TLEN * HROW + i] = 0.f; }
    __syncthreads();

    // ---------------- phase 1: backward sweep ----------------
    for (int t = TLEN - 1; t >= 1; t--) {
        for (int i = tid; i < HROW; i += NT) ghb[(t + 1) * HROW + i] = sm->hsB[i];
        for (int i = tid; i < SROW; i += NT) sm->xs[i] = gst[t * SROW + i];
        __syncthreads();
        gru_step_back<true>(sm->sWb, sm->sU, sm->bB, sm->xs, sm->hsB, sm->stage, nullptr, tid);
    }

    // ---------------- phase 2: forward interpolation ----------------
    for (int i = tid; i < HROW; i += NT) sm->hsF[i] = 0.f;
    for (int i = tid; i < SROW; i += NT) sm->xs[i] = gst[i];
    __syncthreads();
    gru_step_fwd(ureg, gruW, sm->bF, sm->xs, sm->hsF, sm->stage, tid);

    int curr_p = 0;
    while (curr_p < TLEN - 1) {
        if (sm->obs[curr_p + 1]) {
            curr_p++;
            for (int i = tid; i < SROW; i += NT) sm->xs[i] = gst[curr_p * SROW + i];
            __syncthreads();
            gru_step_fwd(ureg, gruW, sm->bF, sm->xs, sm->hsF, sm->stage, tid);
        } else {
            int next_p = curr_p + 1;
            while (next_p < TLEN && !sm->obs[next_p]) next_p++;
            int step = 1;
            while (curr_p + 2 * step <= next_p && step <= 8) step <<= 1;
            if (step > 1) step >>= 1;
            int lvl = (step == 8) ? 3 : (step == 4) ? 2 : (step == 2) ? 1 : 0;

            for (int i = tid; i < HROW; i += NT)
                sm->hb4[i] = ghb[(curr_p + 2 * step) * HROW + i];
            __syncthreads();
            decoder_event(lvl, decW, decB, meanW, meanB, sm->hsF, sm->hb4,
                          sm->dec4, sm->stage, gst + (curr_p + step) * SROW, tid);

            if (step > 1) {
                int right = curr_p + step, left = curr_p + (step >> 1);
                for (int i = tid; i < HROW; i += NT) sm->hsB[i] = ghb[(right + 1) * HROW + i];
                for (int i = tid; i < SROW; i += NT) sm->xs[i] = gst[right * SROW + i];
                __syncthreads();
                gru_step_back<true>(sm->sWb, sm->sU, sm->bB, sm->xs, sm->hsB, sm->stage,
                                    ghb + right * HROW, tid);
                for (int i = right - 1; i >= left; i--) {
                    gru_step_back<false>(sm->sWb, sm->sU, sm->bB, nullptr, sm->hsB, sm->stage,
                                         ghb + i * HROW, tid);
                }
            }
            sm->obs[curr_p + step] = 1;   // all threads write same value
            __syncthreads();
        }
    }

    // ---------------- output: out[b][d][t] = states[t][b][d+1] ----------------
    __syncthreads();
    for (int idx = tid; idx < RPB * DDIM * TLEN; idx += NT) {
        int t = idx & (TLEN - 1);
        int tmp = idx >> 8;
        int d = tmp % DDIM, r = tmp / DDIM;
        int b = b0row + r;
        out[(b * DDIM + d) * TLEN + t] = gst[t * SROW + (d + 1) * RPB + r];
    }
}

extern "C" void kernel_launch(void* const* d_in, const int* in_sizes, int n_in,
                              void* d_out, int out_size)
{
    const float* a     = (const float*)d_in[0];
    const float* gruW  = (const float*)d_in[1];
    const float* gruU  = (const float*)d_in[2];
    const float* gruB  = (const float*)d_in[3];
    const float* bgruW = (const float*)d_in[4];
    const float* bgruU = (const float*)d_in[5];
    const float* bgruB = (const float*)d_in[6];
    const float* decW  = (const float*)d_in[7];
    const float* decB  = (const float*)d_in[8];
    const float* meanW = (const float*)d_in[9];
    const float* meanB = (const float*)d_in[10];
    float* out = (float*)d_out;

    static int smem_set = 0;
    if (!smem_set) {
        cudaFuncSetAttribute(naomi_kernel, cudaFuncAttributeMaxDynamicSharedMemorySize,
                             (int)sizeof(Smem));
        smem_set = 1;
    }
    naomi_kernel<<<NBLK, NT, sizeof(Smem)>>>(a, gruW, gruU, gruB, bgruW, bgruU, bgruB,
                                             decW, decB, meanW, meanB, out);
}

// round 6
// speedup vs baseline: 1.1513x; 1.1513x over previous
#include <cuda_runtime.h>

#define DDIM  64
#define TLEN  256
#define HID   100
#define G3    300
#define NBLK  128
#define RPB   4
#define NT    320
#define STC   65
#define SROW  (STC*RPB)   // 260
#define HROW  (HID*RPB)   // 400
#define GROW  (G3*RPB)    // 1200

typedef unsigned long long u64;

__device__ float g_states[NBLK * TLEN * SROW];
__device__ float g_hback [NBLK * (TLEN + 1) * HROW];
__device__ float g_gi    [(size_t)NBLK * TLEN * GROW];

struct __align__(16) Smem {
    float sU [HID * G3];   // bgru_U
    float sWb[STC * G3];   // bgru_W
    float stGI[GROW];
    float stGH[GROW];
    float hsF[HROW];
    float hsB[HROW];
    float dec4[50 * RPB];
    float bF[2 * G3];
    float bB[2 * G3];
    int   obs[TLEN];
};

__device__ __forceinline__ float tanha(float x) {
    float y; asm("tanh.approx.f32 %0, %1;" : "=f"(y) : "f"(x)); return y;
}
__device__ __forceinline__ u64 pk2(float w) {
    unsigned wi = __float_as_uint(w);
    u64 r; asm("mov.b64 %0, {%1, %1};" : "=l"(r) : "r"(wi), "r"(wi)); return r;
}
__device__ __forceinline__ void fma2(u64& a, u64 v, u64 w) {
    asm("fma.rn.f32x2 %0, %1, %2, %0;" : "+l"(a) : "l"(v), "l"(w));
}

// generic gates phase: gi from vector (smem/global) or from bias (zero-input GRU)
__device__ __forceinline__ void gates_phase(const float* givec, const float* bias0,
                                            const float* gh, const float* hsrc,
                                            float* hout, float* gdict, int tid)
{
    __syncthreads();
#pragma unroll
    for (int pass = 0; pass < 2; pass++) {
        int idx = tid + pass * NT;
        if (idx < HROW) {
            int i = idx >> 2;
            float giz, gir, gin;
            if (givec) { giz = givec[idx]; gir = givec[HROW + idx]; gin = givec[2 * HROW + idx]; }
            else       { giz = bias0[i];   gir = bias0[HID + i];    gin = bias0[2 * HID + i]; }
            float ghz = gh[idx], ghr = gh[HROW + idx], ghn = gh[2 * HROW + idx];
            float z  = fmaf(0.5f, tanha(0.5f * (giz + ghz)), 0.5f);
            float rr = fmaf(0.5f, tanha(0.5f * (gir + ghr)), 0.5f);
            float n  = tanha(fmaf(rr, ghn, gin));
            float hnew = fmaf(z, hsrc[idx] - n, n);
            hout[idx] = hnew;
            if (gdict) gdict[idx] = hnew;
        }
    }
    __syncthreads();
}

// backward GRU step (recompute path). hsrc may be global (first step) or sm->hsB.
template<bool HASX>
__device__ __forceinline__ void back_step(Smem* sm, const float* xg,
                                          const float* hsrc, float* gdict, int tid)
{
    if (tid < G3) {
        if (HASX) {
            u64 gi01 = pk2(sm->bB[tid]), gi23 = gi01;
            const ulonglong2* xv = reinterpret_cast<const ulonglong2*>(xg);
#pragma unroll 5
            for (int k = 0; k < STC; k++) {
                u64 w2 = pk2(sm->sWb[k * G3 + tid]);
                ulonglong2 x = xv[k];
                fma2(gi01, x.x, w2); fma2(gi23, x.y, w2);
            }
            reinterpret_cast<ulonglong2*>(sm->stGI)[tid] = make_ulonglong2(gi01, gi23);
        }
        u64 gh01 = pk2(sm->bB[G3 + tid]), gh23 = gh01;
        const ulonglong2* hv = reinterpret_cast<const ulonglong2*>(hsrc);
#pragma unroll 5
        for (int k = 0; k < HID; k++) {
            u64 u2 = pk2(sm->sU[k * G3 + tid]);
            ulonglong2 h = hv[k];
            fma2(gh01, h.x, u2); fma2(gh23, h.y, u2);
        }
        reinterpret_cast<ulonglong2*>(sm->stGH)[tid] = make_ulonglong2(gh01, gh23);
    }
    gates_phase(HASX ? sm->stGI : (const float*)nullptr, sm->bB,
                sm->stGH, hsrc, sm->hsB, gdict, tid);
}

// sweep step: gi precomputed in g_gi, prefetched into registers to hide DRAM latency
__device__ __forceinline__ void sweep_step(Smem* sm, const float* gv, float* gdict, int tid)
{
    float p0z = gv[tid], p0r = gv[HROW + tid], p0n = gv[2 * HROW + tid];
    float p1z = 0.f, p1r = 0.f, p1n = 0.f;
    if (tid < HROW - NT) {
        p1z = gv[NT + tid]; p1r = gv[HROW + NT + tid]; p1n = gv[2 * HROW + NT + tid];
    }
    if (tid < G3) {
        u64 gh01 = pk2(sm->bB[G3 + tid]), gh23 = gh01;
        const ulonglong2* hv = reinterpret_cast<const ulonglong2*>(sm->hsB);
#pragma unroll 5
        for (int k = 0; k < HID; k++) {
            u64 u2 = pk2(sm->sU[k * G3 + tid]);
            ulonglong2 h = hv[k];
            fma2(gh01, h.x, u2); fma2(gh23, h.y, u2);
        }
        reinterpret_cast<ulonglong2*>(sm->stGH)[tid] = make_ulonglong2(gh01, gh23);
    }
    __syncthreads();
    {
        int idx = tid;
        float ghz = sm->stGH[idx], ghr = sm->stGH[HROW + idx], ghn = sm->stGH[2 * HROW + idx];
        float z  = fmaf(0.5f, tanha(0.5f * (p0z + ghz)), 0.5f);
        float rr = fmaf(0.5f, tanha(0.5f * (p0r + ghr)), 0.5f);
        float n  = tanha(fmaf(rr, ghn, p0n));
        float hnew = fmaf(z, sm->hsB[idx] - n, n);
        sm->hsB[idx] = hnew; gdict[idx] = hnew;
        if (tid < HROW - NT) {
            idx = tid + NT;
            ghz = sm->stGH[idx]; ghr = sm->stGH[HROW + idx]; ghn = sm->stGH[2 * HROW + idx];
            z  = fmaf(0.5f, tanha(0.5f * (p1z + ghz)), 0.5f);
            rr = fmaf(0.5f, tanha(0.5f * (p1r + ghr)), 0.5f);
            n  = tanha(fmaf(rr, ghn, p1n));
            hnew = fmaf(z, sm->hsB[idx] - n, n);
            sm->hsB[idx] = hnew; gdict[idx] = hnew;
        }
    }
    __syncthreads();
}

// forward GRU step: x from global state row (channels 1..64), gru_U column in regs
__device__ __forceinline__ void fwd_step(const float* ureg, const float* __restrict__ gruW,
                                         Smem* sm, const float* xg, int tid)
{
    if (tid < G3) {
        u64 gi01 = pk2(sm->bF[tid]), gi23 = gi01;
        const ulonglong2* xv = reinterpret_cast<const ulonglong2*>(xg);
#pragma unroll 4
        for (int k = 0; k < DDIM; k++) {
            u64 w2 = pk2(__ldg(&gruW[k * G3 + tid]));
            ulonglong2 x = xv[k + 1];
            fma2(gi01, x.x, w2); fma2(gi23, x.y, w2);
        }
        u64 gh01 = pk2(sm->bF[G3 + tid]), gh23 = gh01;
        const ulonglong2* hv = reinterpret_cast<const ulonglong2*>(sm->hsF);
#pragma unroll
        for (int k = 0; k < HID; k++) {          // full unroll: ureg must stay in regs
            u64 u2 = pk2(ureg[k]);
            ulonglong2 h = hv[k];
            fma2(gh01, h.x, u2); fma2(gh23, h.y, u2);
        }
        reinterpret_cast<ulonglong2*>(sm->stGI)[tid] = make_ulonglong2(gi01, gi23);
        reinterpret_cast<ulonglong2*>(sm->stGH)[tid] = make_ulonglong2(gh01, gh23);
    }
    gates_phase(sm->stGI, sm->bF, sm->stGH, sm->hsF, sm->hsF, nullptr, tid);
}

__device__ __forceinline__ void decoder_event(int lvl,
                                              const float* __restrict__ decW,
                                              const float* __restrict__ decB,
                                              const float* __restrict__ meanW,
                                              const float* __restrict__ meanB,
                                              Smem* sm, const float* hbg,
                                              float* gout, int tid)
{
    float* stage = sm->stGI;   // stGI+stGH contiguous scratch
    if (tid < 250) {                          // [4,200]@[200,50], k in 5 groups of 40
        int j = tid % 50, kg = tid / 50;
        u64 a01 = 0, a23 = 0;
        const float* Wl = decW + lvl * 200 * 50;
        int kbeg = kg * 40;
#pragma unroll 8
        for (int kk = 0; kk < 40; kk++) {
            int k = kbeg + kk;
            const float* src = (k < HID) ? (sm->hsF + k * RPB) : (hbg + (k - HID) * RPB);
            ulonglong2 h = *reinterpret_cast<const ulonglong2*>(src);
            u64 w2 = pk2(__ldg(&Wl[k * 50 + j]));
            fma2(a01, h.x, w2); fma2(a23, h.y, w2);
        }
        reinterpret_cast<ulonglong2*>(stage)[tid] = make_ulonglong2(a01, a23);
    }
    __syncthreads();
    if (tid < 50) {
        float b = __ldg(&decB[lvl * 50 + tid]);
        float s0 = b, s1 = b, s2 = b, s3 = b;
#pragma unroll
        for (int g = 0; g < 5; g++) {
            int base = (g * 50 + tid) * 4;
            s0 += stage[base]; s1 += stage[base + 1]; s2 += stage[base + 2]; s3 += stage[base + 3];
        }
        sm->dec4[tid * 4 + 0] = fmaxf(s0, 0.f); sm->dec4[tid * 4 + 1] = fmaxf(s1, 0.f);
        sm->dec4[tid * 4 + 2] = fmaxf(s2, 0.f); sm->dec4[tid * 4 + 3] = fmaxf(s3, 0.f);
    }
    __syncthreads();
    {                                         // [4,50]@[50,64], k in 5 groups of 10
        int j = tid % DDIM, kg = tid / DDIM;
        u64 m01 = 0, m23 = 0;
        const float* Ml = meanW + lvl * 50 * DDIM;
        int kbeg = kg * 10;
#pragma unroll
        for (int kk = 0; kk < 10; kk++) {
            int k = kbeg + kk;
            ulonglong2 d = reinterpret_cast<const ulonglong2*>(sm->dec4)[k];
            u64 w2 = pk2(__ldg(&Ml[k * DDIM + j]));
            fma2(m01, d.x, w2); fma2(m23, d.y, w2);
        }
        reinterpret_cast<ulonglong2*>(stage)[tid] = make_ulonglong2(m01, m23);
    }
    __syncthreads();
    if (tid < DDIM) {
        float b = __ldg(&meanB[lvl * DDIM + tid]);
        float s0 = b, s1 = b, s2 = b, s3 = b;
#pragma unroll
        for (int g = 0; g < 5; g++) {
            int base = (g * DDIM + tid) * 4;
            s0 += stage[base]; s1 += stage[base + 1]; s2 += stage[base + 2]; s3 += stage[base + 3];
        }
        gout[tid * RPB + 0] = s0; gout[tid * RPB + 1] = s1;
        gout[tid * RPB + 2] = s2; gout[tid * RPB + 3] = s3;
    }
    if (tid >= DDIM && tid < DDIM + RPB) gout[DDIM * RPB + (tid - DDIM)] = 1.0f;
    __syncthreads();
}

__global__ void __launch_bounds__(NT, 1)
naomi_kernel(const float* __restrict__ a,
             const float* __restrict__ gruW,  const float* __restrict__ gruU,
             const float* __restrict__ gruB,
             const float* __restrict__ bgruW, const float* __restrict__ bgruU,
             const float* __restrict__ bgruB,
             const float* __restrict__ decW,  const float* __restrict__ decB,
             const float* __restrict__ meanW, const float* __restrict__ meanB,
             float* __restrict__ out)
{
    extern __shared__ __align__(16) char smraw[];
    Smem* sm = reinterpret_cast<Smem*>(smraw);
    const int tid = threadIdx.x;
    const int bid = blockIdx.x;

    for (int i = tid; i < HID * G3; i += NT) sm->sU[i]  = bgruU[i];
    for (int i = tid; i < STC * G3; i += NT) sm->sWb[i] = bgruW[i];
    for (int i = tid; i < 2 * G3;   i += NT) { sm->bF[i] = gruB[i]; sm->bB[i] = bgruB[i]; }

    float ureg[HID];
#pragma unroll
    for (int k = 0; k < HID; k++) ureg[k] = (tid < G3) ? __ldg(&gruU[k * G3 + tid]) : 0.0f;

    for (int t = tid; t < TLEN; t += NT) sm->obs[t] = (a[t * 3 + 2] > 0.5f) ? 1 : 0;

    float* gst = g_states + bid * TLEN * SROW;
    float* ghb = g_hback  + bid * (TLEN + 1) * HROW;
    float* ggi = g_gi     + (size_t)bid * TLEN * GROW;
    const int b0row = bid * RPB;
    for (int idx = tid; idx < RPB * STC * TLEN; idx += NT) {
        int t = idx & (TLEN - 1);
        int tmp = idx >> 8;
        int k = tmp % STC, r = tmp / STC;
        int b = b0row + r;
        float v = (k < DDIM) ? a[((b * DDIM + k) * TLEN + t) * 3]
                             : a[((b * DDIM) * TLEN + t) * 3 + 2];
        gst[t * SROW + k * RPB + r] = v;
    }
    for (int i = tid; i < HROW; i += NT) {
        sm->hsB[i] = 0.f; sm->hsF[i] = 0.f; ghb[TLEN * HROW + i] = 0.f;
    }
    __syncthreads();

    // ---- parallel prepass: gi[t] = states[t] @ bgru_W + b0 for t = 1..255 ----
    for (int task = tid; task < (TLEN - 1) * G3; task += NT) {
        int t = task / G3 + 1;
        int j = task - (t - 1) * G3;
        u64 a01 = pk2(sm->bB[j]), a23 = a01;
        const ulonglong2* xv = reinterpret_cast<const ulonglong2*>(gst + t * SROW);
#pragma unroll 5
        for (int k = 0; k < STC; k++) {
            u64 w2 = pk2(sm->sWb[k * G3 + j]);
            ulonglong2 x = xv[k];
            fma2(a01, x.x, w2); fma2(a23, x.y, w2);
        }
        reinterpret_cast<ulonglong2*>(ggi)[(size_t)t * G3 + j] = make_ulonglong2(a01, a23);
    }
    __syncthreads();

    // ---- phase 1: backward sweep (h-matvec only; gi precomputed) ----
    for (int t = TLEN - 1; t >= 1; t--)
        sweep_step(sm, ggi + (size_t)t * GROW, ghb + t * HROW, tid);

    // ---- phase 2: forward interpolation ----
    fwd_step(ureg, gruW, sm, gst, tid);

    int curr_p = 0;
    while (curr_p < TLEN - 1) {
        if (sm->obs[curr_p + 1]) {
            curr_p++;
            fwd_step(ureg, gruW, sm, gst + curr_p * SROW, tid);
        } else {
            int next_p = curr_p + 1;
            while (next_p < TLEN && !sm->obs[next_p]) next_p++;
            int step = 1;
            while (curr_p + 2 * step <= next_p && step <= 8) step <<= 1;
            if (step > 1) step >>= 1;
            int lvl = (step == 8) ? 3 : (step == 4) ? 2 : (step == 2) ? 1 : 0;

            decoder_event(lvl, decW, decB, meanW, meanB, sm,
                          ghb + (curr_p + 2 * step) * HROW,
                          gst + (curr_p + step) * SROW, tid);

            if (step > 1) {
                int right = curr_p + step, left = curr_p + (step >> 1);
                back_step<true>(sm, gst + right * SROW, ghb + (right + 1) * HROW,
                                ghb + right * HROW, tid);
                for (int i2 = right - 1; i2 >= left; i2--)
                    back_step<false>(sm, nullptr, sm->hsB, ghb + i2 * HROW, tid);
            }
            sm->obs[curr_p + step] = 1;
            __syncthreads();
        }
    }

    // ---- output: out[b][d][t] = states[t][b][d+1] ----
    __syncthreads();
    for (int idx = tid; idx < RPB * DDIM * TLEN; idx += NT) {
        int t = idx & (TLEN - 1);
        int tmp = idx >> 8;
        int d = tmp % DDIM, r = tmp / DDIM;
        int b = b0row + r;
        out[(b * DDIM + d) * TLEN + t] = gst[t * SROW + (d + 1) * RPB + r];
    }
}

extern "C" void kernel_launch(void* const* d_in, const int* in_sizes, int n_in,
                              void* d_out, int out_size)
{
    const float* a     = (const float*)d_in[0];
    const float* gruW  = (const float*)d_in[1];
    const float* gruU  = (const float*)d_in[2];
    const float* gruB  = (const float*)d_in[3];
    const float* bgruW = (const float*)d_in[4];
    const float* bgruU = (const float*)d_in[5];
    const float* bgruB = (const float*)d_in[6];
    const float* decW  = (const float*)d_in[7];
    const float* decB  = (const float*)d_in[8];
    const float* meanW = (const float*)d_in[9];
    const float* meanB = (const float*)d_in[10];
    float* out = (float*)d_out;

    static int smem_set = 0;
    if (!smem_set) {
        cudaFuncSetAttribute(naomi_kernel, cudaFuncAttributeMaxDynamicSharedMemorySize,
                             (int)sizeof(Smem));
        smem_set = 1;
    }
    naomi_kernel<<<NBLK, NT, sizeof(Smem)>>>(a, gruW, gruU, gruB, bgruW, bgruU, bgruB,
                                             decW, decB, meanW, meanB, out);
}

// round 7
// speedup vs baseline: 1.5205x; 1.3207x over previous
#include <cuda_runtime.h>

#define DDIM  64
#define TLEN  256
#define HID   100
#define G3    300
#define NBLK  128
#define RPB   4
#define NT    640
#define STC   65
#define SROW  (STC*RPB)   // 260
#define HROW  (HID*RPB)   // 400
#define GROW  (G3*RPB)    // 1200

typedef unsigned long long u64;

__device__ __align__(16) float g_states[NBLK * TLEN * SROW];
__device__ __align__(16) float g_hback [NBLK * (TLEN + 1) * HROW];
__device__ __align__(16) float g_gi    [(size_t)NBLK * TLEN * GROW];

struct __align__(16) Smem {
    float sU [HID * G3];    // bgru_U (120000 B)
    float sWb[STC * G3];    // bgru_W ( 78000 B)
    float stGI[2 * GROW];   // gi partials, halves   (9600 B)
    float stGH[2 * GROW];   // gh partials, halves   (9600 B)  [contiguous after stGI]
    float hsF[HROW];
    float hsB[HROW];
    float dec4[50 * RPB];
    float bF[2 * G3];
    float bB[2 * G3];
    int   obs[TLEN];
};  // ~227 KB

__device__ __forceinline__ float tanha(float x) {
    float y; asm("tanh.approx.f32 %0, %1;" : "=f"(y) : "f"(x)); return y;
}
__device__ __forceinline__ u64 pk2(float w) {
    unsigned wi = __float_as_uint(w);
    u64 r; asm("mov.b64 %0, {%1, %1};" : "=l"(r) : "r"(wi), "r"(wi)); return r;
}
__device__ __forceinline__ void fma2(u64& a, u64 v, u64 w) {
    asm("fma.rn.f32x2 %0, %1, %2, %0;" : "+l"(a) : "l"(v), "l"(w));
}

// ---- gates: combine split partials, apply nonlinearity, update h (and h_back dict) ----
// giMode: 0 = combine stGI halves, 1 = bias-only (zero-input GRU), 2 = full gi vector in gv
__device__ __forceinline__ void gates_apply(Smem* sm, int giMode, const float* gv,
                                            const float* bias, const float* hsrc,
                                            float* hout, float* gdict, int tid,
                                            float pgz, float pgr, float pgn)
{
    if (tid < HROW) {
        int idx = tid;
        float giz, gir, gin;
        if (giMode == 0) {
            giz = sm->stGI[idx]            + sm->stGI[GROW + idx];
            gir = sm->stGI[HROW + idx]     + sm->stGI[GROW + HROW + idx];
            gin = sm->stGI[2 * HROW + idx] + sm->stGI[GROW + 2 * HROW + idx];
        } else if (giMode == 1) {
            int i = idx >> 2;
            giz = bias[i]; gir = bias[HID + i]; gin = bias[2 * HID + i];
        } else {   // prefetched into pgz/pgr/pgn
            giz = pgz; gir = pgr; gin = pgn;
        }
        float ghz = sm->stGH[idx]            + sm->stGH[GROW + idx];
        float ghr = sm->stGH[HROW + idx]     + sm->stGH[GROW + HROW + idx];
        float ghn = sm->stGH[2 * HROW + idx] + sm->stGH[GROW + 2 * HROW + idx];
        float z  = fmaf(0.5f, tanha(0.5f * (giz + ghz)), 0.5f);
        float rr = fmaf(0.5f, tanha(0.5f * (gir + ghr)), 0.5f);
        float n  = tanha(fmaf(rr, ghn, gin));
        float hnew = fmaf(z, hsrc[idx] - n, n);
        hout[idx] = hnew;
        if (gdict) gdict[idx] = hnew;
    }
    __syncthreads();
}

// ---- sweep step: gi precomputed in g_gi; split gh matvec over 600 threads ----
__device__ __forceinline__ void sweep_step(Smem* sm, const float* __restrict__ gv,
                                           float* gdict, int tid, int half, int j)
{
    float pgz = 0.f, pgr = 0.f, pgn = 0.f;
    if (tid < HROW) {
        pgz = __ldg(gv + tid); pgr = __ldg(gv + HROW + tid); pgn = __ldg(gv + 2 * HROW + tid);
    }
    if (tid < 600) {
        u64 gh01 = half ? 0ull : pk2(sm->bB[G3 + j]);
        u64 gh23 = gh01;
        const ulonglong2* hv = reinterpret_cast<const ulonglong2*>(sm->hsB) + half * 50;
        const float* Uc = sm->sU + half * 50 * G3 + j;
#pragma unroll 5
        for (int k = 0; k < 50; k++) {
            u64 u2 = pk2(Uc[k * G3]);
            ulonglong2 h = hv[k];
            fma2(gh01, h.x, u2); fma2(gh23, h.y, u2);
        }
        reinterpret_cast<ulonglong2*>(sm->stGH)[half * G3 + j] = make_ulonglong2(gh01, gh23);
    }
    __syncthreads();
    gates_apply(sm, 2, nullptr, sm->bB, sm->hsB, sm->hsB, gdict, tid, pgz, pgr, pgn);
}

// ---- backward GRU step (recompute path) ----
template<bool HASX>
__device__ __forceinline__ void back_step(Smem* sm, const float* xg, const float* hsrc,
                                          float* gdict, int tid, int half, int j)
{
    if (tid < 600) {
        if (HASX) {
            int kb = half ? 33 : 0, kn = half ? 32 : 33;
            u64 gi01 = half ? 0ull : pk2(sm->bB[j]);
            u64 gi23 = gi01;
            const ulonglong2* xv = reinterpret_cast<const ulonglong2*>(xg) + kb;
            const float* Wc = sm->sWb + kb * G3 + j;
#pragma unroll 3
            for (int k = 0; k < kn; k++) {
                u64 w2 = pk2(Wc[k * G3]);
                ulonglong2 x = xv[k];
                fma2(gi01, x.x, w2); fma2(gi23, x.y, w2);
            }
            reinterpret_cast<ulonglong2*>(sm->stGI)[half * G3 + j] = make_ulonglong2(gi01, gi23);
        }
        u64 gh01 = (half || !HASX) ? (half ? 0ull : pk2(sm->bB[G3 + j])) : pk2(sm->bB[G3 + j]);
        if (half) gh01 = 0ull;
        u64 gh23 = gh01;
        const ulonglong2* hv = reinterpret_cast<const ulonglong2*>(hsrc) + half * 50;
        const float* Uc = sm->sU + half * 50 * G3 + j;
#pragma unroll 5
        for (int k = 0; k < 50; k++) {
            u64 u2 = pk2(Uc[k * G3]);
            ulonglong2 h = hv[k];
            fma2(gh01, h.x, u2); fma2(gh23, h.y, u2);
        }
        reinterpret_cast<ulonglong2*>(sm->stGH)[half * G3 + j] = make_ulonglong2(gh01, gh23);
    }
    __syncthreads();
    gates_apply(sm, HASX ? 0 : 1, nullptr, sm->bB, hsrc, sm->hsB, gdict, tid, 0.f, 0.f, 0.f);
}

// ---- forward GRU step ----
__device__ __forceinline__ void fwd_step(const float* ureg, const float* __restrict__ gruW,
                                         Smem* sm, const float* xg, int tid, int half, int j)
{
    if (tid < 600) {
        u64 gi01 = half ? 0ull : pk2(sm->bF[j]);
        u64 gi23 = gi01;
        const ulonglong2* xv = reinterpret_cast<const ulonglong2*>(xg) + 1 + half * 32;
        const float* Wc = gruW + half * 32 * G3 + j;
#pragma unroll 4
        for (int k = 0; k < 32; k++) {
            u64 w2 = pk2(__ldg(Wc + k * G3));
            ulonglong2 x = xv[k];
            fma2(gi01, x.x, w2); fma2(gi23, x.y, w2);
        }
        u64 gh01 = half ? 0ull : pk2(sm->bF[G3 + j]);
        u64 gh23 = gh01;
        const ulonglong2* hv = reinterpret_cast<const ulonglong2*>(sm->hsF) + half * 50;
#pragma unroll
        for (int k = 0; k < 50; k++) {
            u64 u2 = pk2(ureg[k]);
            ulonglong2 h = hv[k];
            fma2(gh01, h.x, u2); fma2(gh23, h.y, u2);
        }
        reinterpret_cast<ulonglong2*>(sm->stGI)[half * G3 + j] = make_ulonglong2(gi01, gi23);
        reinterpret_cast<ulonglong2*>(sm->stGH)[half * G3 + j] = make_ulonglong2(gh01, gh23);
    }
    __syncthreads();
    gates_apply(sm, 0, nullptr, sm->bF, sm->hsF, sm->hsF, nullptr, tid, 0.f, 0.f, 0.f);
}

// ---- decoder event ----
__device__ __forceinline__ void decoder_event(int lvl,
                                              const float* __restrict__ decW,
                                              const float* __restrict__ decB,
                                              const float* __restrict__ meanW,
                                              const float* __restrict__ meanB,
                                              Smem* sm, const float* hbg,
                                              float* gout, int tid)
{
    float* stage = sm->stGI;          // stGI+stGH contiguous scratch (19200 B)
    if (tid < 500) {                  // [4,200]@[200,50], k in 10 groups of 20
        int j = tid % 50, kg = tid / 50;
        u64 a01 = 0, a23 = 0;
        const float* Wl = decW + lvl * 200 * 50;
        int kbeg = kg * 20;
#pragma unroll 5
        for (int kk = 0; kk < 20; kk++) {
            int k = kbeg + kk;
            const float* src = (k < HID) ? (sm->hsF + k * RPB) : (hbg + (k - HID) * RPB);
            ulonglong2 h = *reinterpret_cast<const ulonglong2*>(src);
            u64 w2 = pk2(__ldg(&Wl[k * 50 + j]));
            fma2(a01, h.x, w2); fma2(a23, h.y, w2);
        }
        reinterpret_cast<ulonglong2*>(stage)[tid] = make_ulonglong2(a01, a23);
    }
    __syncthreads();
    if (tid < 50) {
        float b = __ldg(&decB[lvl * 50 + tid]);
        float s0 = b, s1 = b, s2 = b, s3 = b;
#pragma unroll
        for (int g = 0; g < 10; g++) {
            int base = (g * 50 + tid) * 4;
            s0 += stage[base]; s1 += stage[base + 1]; s2 += stage[base + 2]; s3 += stage[base + 3];
        }
        sm->dec4[tid * 4 + 0] = fmaxf(s0, 0.f); sm->dec4[tid * 4 + 1] = fmaxf(s1, 0.f);
        sm->dec4[tid * 4 + 2] = fmaxf(s2, 0.f); sm->dec4[tid * 4 + 3] = fmaxf(s3, 0.f);
    }
    __syncthreads();
    {                                 // [4,50]@[50,64], k in 10 groups of 5 (640 threads)
        int j = tid & 63, kg = tid >> 6;
        u64 m01 = 0, m23 = 0;
        const float* Ml = meanW + lvl * 50 * DDIM;
        int kbeg = kg * 5;
#pragma unroll
        for (int kk = 0; kk < 5; kk++) {
            int k = kbeg + kk;
            ulonglong2 d = reinterpret_cast<const ulonglong2*>(sm->dec4)[k];
            u64 w2 = pk2(__ldg(&Ml[k * DDIM + j]));
            fma2(m01, d.x, w2); fma2(m23, d.y, w2);
        }
        reinterpret_cast<ulonglong2*>(stage)[tid] = make_ulonglong2(m01, m23);
    }
    __syncthreads();
    if (tid < DDIM) {
        float b = __ldg(&meanB[lvl * DDIM + tid]);
        float s0 = b, s1 = b, s2 = b, s3 = b;
#pragma unroll
        for (int g = 0; g < 10; g++) {
            int base = (g * DDIM + tid) * 4;
            s0 += stage[base]; s1 += stage[base + 1]; s2 += stage[base + 2]; s3 += stage[base + 3];
        }
        gout[tid * RPB + 0] = s0; gout[tid * RPB + 1] = s1;
        gout[tid * RPB + 2] = s2; gout[tid * RPB + 3] = s3;
    }
    if (tid >= DDIM && tid < DDIM + RPB) gout[DDIM * RPB + (tid - DDIM)] = 1.0f;
    __syncthreads();
}

__global__ void __launch_bounds__(NT, 1)
naomi_kernel(const float* __restrict__ a,
             const float* __restrict__ gruW,  const float* __restrict__ gruU,
             const float* __restrict__ gruB,
             const float* __restrict__ bgruW, const float* __restrict__ bgruU,
             const float* __restrict__ bgruB,
             const float* __restrict__ decW,  const float* __restrict__ decB,
             const float* __restrict__ meanW, const float* __restrict__ meanB,
             float* __restrict__ out)
{
    extern __shared__ __align__(16) char smraw[];
    Smem* sm = reinterpret_cast<Smem*>(smraw);
    const int tid = threadIdx.x;
    const int bid = blockIdx.x;
    const int half = (tid < 600) ? (tid >= 300) : 0;
    const int j    = (tid < 600) ? (tid - half * 300) : 0;

    for (int i = tid; i < HID * G3; i += NT) sm->sU[i]  = bgruU[i];
    for (int i = tid; i < STC * G3; i += NT) sm->sWb[i] = bgruW[i];
    for (int i = tid; i < 2 * G3;   i += NT) { sm->bF[i] = gruB[i]; sm->bB[i] = bgruB[i]; }

    float ureg[50];
#pragma unroll
    for (int kk = 0; kk < 50; kk++)
        ureg[kk] = (tid < 600) ? __ldg(&gruU[(half * 50 + kk) * G3 + j]) : 0.0f;

    for (int t = tid; t < TLEN; t += NT) sm->obs[t] = (a[t * 3 + 2] > 0.5f) ? 1 : 0;

    float* gst = g_states + bid * TLEN * SROW;
    float* ghb = g_hback  + bid * (TLEN + 1) * HROW;
    float* ggi = g_gi     + (size_t)bid * TLEN * GROW;
    const int b0row = bid * RPB;
    for (int idx = tid; idx < RPB * STC * TLEN; idx += NT) {
        int t = idx & (TLEN - 1);
        int tmp = idx >> 8;
        int k = tmp % STC, r = tmp / STC;
        int b = b0row + r;
        float v = (k < DDIM) ? a[((b * DDIM + k) * TLEN + t) * 3]
                             : a[((b * DDIM) * TLEN + t) * 3 + 2];
        gst[t * SROW + k * RPB + r] = v;
    }
    for (int i = tid; i < HROW; i += NT) {
        sm->hsB[i] = 0.f; sm->hsF[i] = 0.f; ghb[TLEN * HROW + i] = 0.f;
    }
    __syncthreads();

    // ---- parallel prepass: gi[t] = states[t] @ bgru_W + b0, t = 1..255 ----
    for (int task = tid; task < (TLEN - 1) * G3; task += NT) {
        int t = task / G3 + 1;
        int jj = task - (t - 1) * G3;
        u64 a01 = pk2(sm->bB[jj]), a23 = a01;
        const ulonglong2* xv = reinterpret_cast<const ulonglong2*>(gst + t * SROW);
#pragma unroll 5
        for (int k = 0; k < STC; k++) {
            u64 w2 = pk2(sm->sWb[k * G3 + jj]);
            ulonglong2 x = xv[k];
            fma2(a01, x.x, w2); fma2(a23, x.y, w2);
        }
        reinterpret_cast<ulonglong2*>(ggi)[(size_t)t * G3 + jj] = make_ulonglong2(a01, a23);
    }
    __syncthreads();

    // ---- phase 1: backward sweep ----
    for (int t = TLEN - 1; t >= 1; t--)
        sweep_step(sm, ggi + (size_t)t * GROW, ghb + t * HROW, tid, half, j);

    // ---- phase 2: forward interpolation ----
    fwd_step(ureg, gruW, sm, gst, tid, half, j);

    int curr_p = 0;
    while (curr_p < TLEN - 1) {
        if (sm->obs[curr_p + 1]) {
            curr_p++;
            fwd_step(ureg, gruW, sm, gst + curr_p * SROW, tid, half, j);
        } else {
            int next_p = curr_p + 1;
            while (next_p < TLEN && !sm->obs[next_p]) next_p++;
            int step = 1;
            while (curr_p + 2 * step <= next_p && step <= 8) step <<= 1;
            if (step > 1) step >>= 1;
            int lvl = (step == 8) ? 3 : (step == 4) ? 2 : (step == 2) ? 1 : 0;

            decoder_event(lvl, decW, decB, meanW, meanB, sm,
                          ghb + (curr_p + 2 * step) * HROW,
                          gst + (curr_p + step) * SROW, tid);

            if (step > 1) {
                int right = curr_p + step, left = curr_p + (step >> 1);
                back_step<true>(sm, gst + right * SROW, ghb + (right + 1) * HROW,
                                ghb + right * HROW, tid, half, j);
                for (int i2 = right - 1; i2 >= left; i2--)
                    back_step<false>(sm, nullptr, sm->hsB, ghb + i2 * HROW, tid, half, j);
            }
            sm->obs[curr_p + step] = 1;
            __syncthreads();
        }
    }

    // ---- output: out[b][d][t] = states[t][b][d+1] ----
    __syncthreads();
    for (int idx = tid; idx < RPB * DDIM * TLEN; idx += NT) {
        int t = idx & (TLEN - 1);
        int tmp = idx >> 8;
        int d = tmp % DDIM, r = tmp / DDIM;
        int b = b0row + r;
        out[(b * DDIM + d) * TLEN + t] = gst[t * SROW + (d + 1) * RPB + r];
    }
}

extern "C" void kernel_launch(void* const* d_in, const int* in_sizes, int n_in,
                              void* d_out, int out_size)
{
    const float* a     = (const float*)d_in[0];
    const float* gruW  = (const float*)d_in[1];
    const float* gruU  = (const float*)d_in[2];
    const float* gruB  = (const float*)d_in[3];
    const float* bgruW = (const float*)d_in[4];
    const float* bgruU = (const float*)d_in[5];
    const float* bgruB = (const float*)d_in[6];
    const float* decW  = (const float*)d_in[7];
    const float* decB  = (const float*)d_in[8];
    const float* meanW = (const float*)d_in[9];
    const float* meanB = (const float*)d_in[10];
    float* out = (float*)d_out;

    static int smem_set = 0;
    if (!smem_set) {
        cudaFuncSetAttribute(naomi_kernel, cudaFuncAttributeMaxDynamicSharedMemorySize,
                             (int)sizeof(Smem));
        smem_set = 1;
    }
    naomi_kernel<<<NBLK, NT, sizeof(Smem)>>>(a, gruW, gruU, gruB, bgruW, bgruU, bgruB,
                                             decW, decB, meanW, meanB, out);
}